// round 8
// baseline (speedup 1.0000x reference)
#include <cuda_runtime.h>
#include <cuda_fp16.h>
#include <cstdint>

#define BATCH   65536
#define DIM     128
#define NPROTO  512
#define ODIM    8
#define MTILE   128
#define NCHUNK  32
#define NCHUNKS 16
#define NTHREADS 256

#define ASTRIDE 272
#define ATILE   (MTILE * ASTRIDE)      // 34816
#define BTILE   (NCHUNK * ASTRIDE)     // 8704

#define SM_BIAS 0
#define SM_NRM  2048
#define SM_A    2560
#define SM_B    (SM_A + ATILE)         // 37376
#define SM_RED  SM_A
#define SMEM_TOTAL (SM_B + 2 * BTILE)  // 54784 -> 2 CTAs/SM

#define P2ROWS   8
#define P2BLOCKS 1024
#define P2SMEM   ((1024 + 16384 + 512) * 4)   // 71680

__device__ __align__(16) __half g_h[NPROTO * DIM];   // fp16 high split of w
__device__ __align__(16) float  g_wf[NPROTO * DIM];  // exact fp32 w
__device__ float g_bias[NPROTO];
__device__ int   g_maxMw = 0;
__device__ int   g_maxW  = 0;
__device__ int   g_nflag;
__device__ int   g_list[BATCH];

// ---------------- helpers ----------------
__device__ __forceinline__ uint32_t smem_u32(const void* p) {
    uint32_t a;
    asm("{ .reg .u64 t; cvta.to.shared.u64 t, %1; cvt.u32.u64 %0, t; }" : "=r"(a) : "l"(p));
    return a;
}
__device__ __forceinline__ void ldsm4(uint32_t* r, uint32_t a) {
    asm volatile("ldmatrix.sync.aligned.m8n8.x4.shared.b16 {%0,%1,%2,%3}, [%4];"
                 : "=r"(r[0]), "=r"(r[1]), "=r"(r[2]), "=r"(r[3]) : "r"(a));
}
__device__ __forceinline__ void mma16816(float* d, const uint32_t* a, const uint32_t* b) {
    asm volatile(
        "mma.sync.aligned.m16n8k16.row.col.f32.f16.f16.f32 "
        "{%0,%1,%2,%3}, {%4,%5,%6,%7}, {%8,%9}, {%0,%1,%2,%3};"
        : "+f"(d[0]), "+f"(d[1]), "+f"(d[2]), "+f"(d[3])
        : "r"(a[0]), "r"(a[1]), "r"(a[2]), "r"(a[3]), "r"(b[0]), "r"(b[1]));
}
__device__ __forceinline__ void cp_async16(uint32_t dst, const void* src) {
    asm volatile("cp.async.cg.shared.global [%0], [%1], 16;" :: "r"(dst), "l"(src));
}

// ---------------------------------------------------------------------------
// Prep: H = fp16(w), exact w, bias, norm maxima; reset flag counter.
// ---------------------------------------------------------------------------
__global__ void prep_kernel(const float* __restrict__ protos,
                            const float* __restrict__ relevance) {
    int p = blockIdx.x;
    int d = threadIdx.x;
    if (p == 0 && d == 0) g_nflag = 0;

    float r  = relevance[d];
    float pv = protos[p * DIM + d];
    float w  = r * r * pv;

    __half h  = __float2half_rn(w);
    float  Mw = w - __half2float(h);
    g_h[p * DIM + d]  = h;
    g_wf[p * DIM + d] = w;

    float sb = w * pv, sm = Mw * Mw, sw = w * w;
    __shared__ float r0[4], r1[4], r2[4];
    #pragma unroll
    for (int off = 16; off > 0; off >>= 1) {
        sb += __shfl_down_sync(0xffffffffu, sb, off);
        sm += __shfl_down_sync(0xffffffffu, sm, off);
        sw += __shfl_down_sync(0xffffffffu, sw, off);
    }
    if ((d & 31) == 0) { r0[d >> 5] = sb; r1[d >> 5] = sm; r2[d >> 5] = sw; }
    __syncthreads();
    if (d == 0) {
        g_bias[p] = -0.5f * (r0[0] + r0[1] + r0[2] + r0[3]);
        float nm = sqrtf(r1[0] + r1[1] + r1[2] + r1[3]) * 1.0001f;
        float nw = sqrtf(r2[0] + r2[1] + r2[2] + r2[3]) * 1.0001f;
        atomicMax(&g_maxMw, __float_as_int(nm));
        atomicMax(&g_maxW,  __float_as_int(nw));
    }
}

// ---------------------------------------------------------------------------
// Phase 1: hh-only fp16 GEMM (R5 tiling) + branchless top-2 + certification.
//   256 threads, 2 CTAs/SM, warps 4M x 2N, warp tile 32x16, chunk N=32.
// ---------------------------------------------------------------------------
extern __shared__ char smem[];

__global__ void __launch_bounds__(NTHREADS, 2)
grlvq_phase1(const float* __restrict__ x,
             const float* __restrict__ proto_out,
             float* __restrict__ out) {
    const uint32_t sb = smem_u32(smem);
    const int tid  = threadIdx.x;
    const int wid  = tid >> 5;
    const int lane = tid & 31;
    const int row0 = blockIdx.x * MTILE;
    const int wm = (wid & 3) * 32;
    const int wn = (wid >> 2) * 16;

    for (int i = tid; i < NPROTO; i += NTHREADS)
        ((float*)(smem + SM_BIAS))[i] = g_bias[i];

    // B chunk: 32 rows x 16 uint4 = 512 cp.async per chunk
    #define ISSUE_B(c, buf)                                                        \
        do {                                                                       \
            for (int i = tid; i < 512; i += NTHREADS) {                            \
                int rr = i >> 4, q = i & 15;                                       \
                const void* src = &g_h[(size_t)((c) * NCHUNK + rr) * DIM + q * 8]; \
                uint32_t dst = sb + SM_B + (buf) * BTILE + rr * ASTRIDE + q * 16;  \
                cp_async16(dst, src);                                              \
            }                                                                      \
            asm volatile("cp.async.commit_group;" ::: "memory");                   \
        } while (0)

    ISSUE_B(0, 0);
    ISSUE_B(1, 1);

    // ---- A: load x tile, keep fp16 high split; row norms for bound ----
    {
        const int r  = tid >> 1;
        const int cb = (tid & 1) * 64;
        const float4* xr = (const float4*)(x + (size_t)(row0 + r) * DIM + cb);
        float sx2 = 0.0f, sm2 = 0.0f;
        #pragma unroll
        for (int g = 0; g < 8; g++) {
            float4 v0 = xr[g * 2], v1 = xr[g * 2 + 1];
            float xv[8] = {v0.x, v0.y, v0.z, v0.w, v1.x, v1.y, v1.z, v1.w};
            uint32_t hh[4];
            #pragma unroll
            for (int q = 0; q < 4; q++) {
                float a0 = xv[2 * q], a1 = xv[2 * q + 1];
                __half h0 = __float2half_rn(a0), h1 = __float2half_rn(a1);
                float m0 = a0 - __half2float(h0), m1 = a1 - __half2float(h1);
                sx2 += a0 * a0 + a1 * a1;
                sm2 += m0 * m0 + m1 * m1;
                hh[q] = ((uint32_t)__half_as_ushort(h1) << 16) | __half_as_ushort(h0);
            }
            uint32_t off = (uint32_t)r * ASTRIDE + (uint32_t)(cb + g * 8) * 2;
            *(uint4*)(smem + SM_A + off) = make_uint4(hh[0], hh[1], hh[2], hh[3]);
        }
        sx2 += __shfl_xor_sync(0xffffffffu, sx2, 1);
        sm2 += __shfl_xor_sync(0xffffffffu, sm2, 1);
        if ((tid & 1) == 0) {
            float maxMw = __int_as_float(g_maxMw);
            float maxW  = __int_as_float(g_maxW);
            ((float*)(smem + SM_NRM))[r] =
                1.0002f * sqrtf(sx2) * maxMw + 1.0002f * sqrtf(sm2) * maxW + 0.01f;
        }
    }

    float v1s[4], v2s[4];
    int   i1s[4];
    #pragma unroll
    for (int i = 0; i < 4; i++) { v1s[i] = -3.4e38f; v2s[i] = -3.4e38f; i1s[i] = 0; }

    const uint32_t a_row = (uint32_t)(wm + (lane & 15));
    const uint32_t a_kh  = (uint32_t)(lane >> 4) * 16;
    const uint32_t b_row = (uint32_t)(wn + ((lane >> 4) & 1) * 8 + (lane & 7));
    const uint32_t b_kh  = (uint32_t)((lane >> 3) & 1) * 16;

    // branchless top-2 insert (ascending col => 'v > v1' keeps first index)
    #define INS(v, c, s) do {                                   \
        float _mn = fminf((v), v1s[s]);                         \
        i1s[s] = ((v) > v1s[s]) ? (c) : i1s[s];                 \
        v1s[s] = fmaxf(v1s[s], (v));                            \
        v2s[s] = fmaxf(v2s[s], _mn);                            \
    } while (0)

    for (int c = 0; c < NCHUNKS; c++) {
        asm volatile("cp.async.wait_group 1;" ::: "memory");
        __syncthreads();
        const uint32_t bbase = sb + SM_B + (c & 1) * BTILE;

        float acc[2][2][4];
        #pragma unroll
        for (int mt = 0; mt < 2; mt++)
            #pragma unroll
            for (int nt = 0; nt < 2; nt++)
                #pragma unroll
                for (int j = 0; j < 4; j++) acc[mt][nt][j] = 0.0f;

        #pragma unroll
        for (int kk = 0; kk < 8; kk++) {
            uint32_t af[2][4], bf[4];
            #pragma unroll
            for (int mt = 0; mt < 2; mt++)
                ldsm4(af[mt], sb + SM_A + (a_row + mt * 16) * ASTRIDE + kk * 32 + a_kh);
            ldsm4(bf, bbase + b_row * ASTRIDE + kk * 32 + b_kh);
            #pragma unroll
            for (int mt = 0; mt < 2; mt++)
                #pragma unroll
                for (int nt = 0; nt < 2; nt++)
                    mma16816(acc[mt][nt], af[mt], &bf[nt * 2]);
        }

        const float* bias_s = (const float*)(smem + SM_BIAS);
        #pragma unroll
        for (int mt = 0; mt < 2; mt++) {
            #pragma unroll
            for (int nt = 0; nt < 2; nt++) {
                const int col = c * NCHUNK + wn + nt * 8 + (lane & 3) * 2;
                float b0 = bias_s[col], b1 = bias_s[col + 1];
                float v0 = acc[mt][nt][0] + b0;
                float v1 = acc[mt][nt][1] + b1;
                float v2 = acc[mt][nt][2] + b0;
                float v3 = acc[mt][nt][3] + b1;
                INS(v0, col,     mt * 2);
                INS(v1, col + 1, mt * 2);
                INS(v2, col,     mt * 2 + 1);
                INS(v3, col + 1, mt * 2 + 1);
            }
        }

        __syncthreads();
        if (c + 2 < NCHUNKS) ISSUE_B(c + 2, c & 1);
    }

    // ---- cross-thread top-2 merge: 8 owners per row ----
    float* rv1 = (float*)(smem + SM_RED);
    int*   ri1 = (int*)(smem + SM_RED + 4096);
    float* rv2 = (float*)(smem + SM_RED + 8192);
    const int slot = ((wid >> 2) << 2) | (lane & 3);
    #pragma unroll
    for (int sl = 0; sl < 4; sl++) {
        int row = wm + (sl >> 1) * 16 + (sl & 1) * 8 + (lane >> 2);
        rv1[row * 8 + slot] = v1s[sl];
        ri1[row * 8 + slot] = i1s[sl];
        rv2[row * 8 + slot] = v2s[sl];
    }
    __syncthreads();

    if (tid < MTILE) {
        float b1 = -3.4e38f, b2 = -3.4e38f;
        int   bi = 0;
        #pragma unroll
        for (int j = 0; j < 8; j++) {
            float v = rv1[tid * 8 + j];
            int  ix = ri1[tid * 8 + j];
            bool g = v > b1;
            b2 = fmaxf(b2, fminf(v, b1));
            b1 = fmaxf(b1, v);
            bi = g ? ix : bi;
        }
        #pragma unroll
        for (int j = 0; j < 8; j++)
            b2 = fmaxf(b2, rv2[tid * 8 + j]);

        float Br = ((const float*)(smem + SM_NRM))[tid];
        bool flag = !(b1 - b2 > 2.0f * Br);

        unsigned m = __ballot_sync(0xffffffffu, flag);
        int cnt = __popc(m);
        if (cnt) {
            int base = 0;
            if (lane == 0) base = atomicAdd(&g_nflag, cnt);
            base = __shfl_sync(0xffffffffu, base, 0);
            if (flag)
                g_list[base + __popc(m & ((1u << lane) - 1u))] = row0 + tid;
        }

        const float4* po = (const float4*)proto_out;
        float4* o = (float4*)(out + (size_t)(row0 + tid) * ODIM);
        o[0] = po[bi * 2];
        o[1] = po[bi * 2 + 1];
    }
}

// ---------------------------------------------------------------------------
// Phase 2: exact fp32 rescore of flagged rows, 8 rows/block, warp-per-row.
// ---------------------------------------------------------------------------
extern __shared__ float s2[];

__global__ void __launch_bounds__(256)
grlvq_phase2(const float* __restrict__ x,
             const float* __restrict__ proto_out,
             float* __restrict__ out) {
    float* sx    = s2;                     // 8 x 128
    float* sw    = s2 + 1024;              // [128 dims][128 protos]
    float* sbias = s2 + 1024 + 16384;      // 512

    const int tid  = threadIdx.x;
    const int wid  = tid >> 5;             // warp = row owner (0..7)
    const int lane = tid & 31;
    const int nflag = g_nflag;

    for (int i = tid; i < NPROTO; i += 256) sbias[i] = g_bias[i];

    for (int base = blockIdx.x * P2ROWS; base < nflag; base += P2BLOCKS * P2ROWS) {
        __syncthreads();
        const int nr = min(P2ROWS, nflag - base);

        // load flagged x rows: 8 x 32 float4 = 256
        if (tid < nr * 32) {
            int r = tid >> 5, q = tid & 31;
            int row = g_list[base + r];
            ((float4*)sx)[tid] = ((const float4*)(x + (size_t)row * DIM))[q];
        }

        float bv = -3.4e38f;
        int   bi = 0;

        for (int c = 0; c < 4; c++) {
            __syncthreads();
            {   // transpose-load w chunk: sw[d][p] for protos c*128..c*128+127
                int pr = tid >> 1;
                int d0 = (tid & 1) * 64;
                const float4* wsrc =
                    (const float4*)&g_wf[(size_t)(c * 128 + pr) * DIM + d0];
                #pragma unroll
                for (int q = 0; q < 16; q++) {
                    float4 v = wsrc[q];
                    int d = d0 + q * 4;
                    sw[(d + 0) * 128 + pr] = v.x;
                    sw[(d + 1) * 128 + pr] = v.y;
                    sw[(d + 2) * 128 + pr] = v.z;
                    sw[(d + 3) * 128 + pr] = v.w;
                }
            }
            __syncthreads();

            float a0 = 0.f, a1 = 0.f, a2 = 0.f, a3 = 0.f;
            #pragma unroll 8
            for (int dd = 0; dd < 128; dd++) {
                float xv = sx[wid * 128 + dd];
                float4 w = *(const float4*)&sw[dd * 128 + lane * 4];
                a0 += xv * w.x; a1 += xv * w.y; a2 += xv * w.z; a3 += xv * w.w;
            }
            int p = c * 128 + lane * 4;
            float s0 = a0 + sbias[p];
            float s1 = a1 + sbias[p + 1];
            float s2v = a2 + sbias[p + 2];
            float s3 = a3 + sbias[p + 3];
            if (s0 > bv) { bv = s0; bi = p; }
            if (s1 > bv) { bv = s1; bi = p + 1; }
            if (s2v > bv) { bv = s2v; bi = p + 2; }
            if (s3 > bv) { bv = s3; bi = p + 3; }
        }

        // warp-level argmax reduce (min index on ties)
        #pragma unroll
        for (int off = 16; off > 0; off >>= 1) {
            float ov = __shfl_down_sync(0xffffffffu, bv, off);
            int   oi = __shfl_down_sync(0xffffffffu, bi, off);
            if (ov > bv || (ov == bv && oi < bi)) { bv = ov; bi = oi; }
        }
        bi = __shfl_sync(0xffffffffu, bi, 0);

        if (wid < nr && lane < 2) {
            int row = g_list[base + wid];
            const float4* po = (const float4*)proto_out;
            ((float4*)(out + (size_t)row * ODIM))[lane] = po[bi * 2 + lane];
        }
    }
}

// ---------------------------------------------------------------------------
extern "C" void kernel_launch(void* const* d_in, const int* in_sizes, int n_in,
                              void* d_out, int out_size) {
    const float* x         = (const float*)d_in[0];
    const float* protos    = (const float*)d_in[1];
    const float* proto_out = (const float*)d_in[2];
    const float* relevance = (const float*)d_in[3];
    float* out = (float*)d_out;

    prep_kernel<<<NPROTO, DIM>>>(protos, relevance);

    cudaFuncSetAttribute(grlvq_phase1,
                         cudaFuncAttributeMaxDynamicSharedMemorySize, SMEM_TOTAL);
    grlvq_phase1<<<BATCH / MTILE, NTHREADS, SMEM_TOTAL>>>(x, proto_out, out);

    cudaFuncSetAttribute(grlvq_phase2,
                         cudaFuncAttributeMaxDynamicSharedMemorySize, P2SMEM);
    grlvq_phase2<<<P2BLOCKS, 256, P2SMEM>>>(x, proto_out, out);
}

// round 9
// speedup vs baseline: 1.0750x; 1.0750x over previous
#include <cuda_runtime.h>
#include <cuda_fp16.h>
#include <cstdint>

#define BATCH   65536
#define DIM     128
#define NPROTO  512
#define ODIM    8
#define MTILE   128
#define NCHUNK  64
#define NCHUNKS 8
#define NTHREADS 256

#define ASTRIDE 272
#define ATILE   (MTILE * ASTRIDE)      // 34816
#define BTILE   (NCHUNK * ASTRIDE)     // 17408

#define SM_BIAS 0
#define SM_NRM  2048
#define SM_A    2560
#define SM_B    (SM_A + ATILE)         // 37376
#define SM_RED  SM_A
#define SMEM_TOTAL (SM_B + 2 * BTILE)  // 72192 -> 2 CTAs/SM

#define P2ROWS   8
#define P2BLOCKS 1024
#define P2SMEM   ((1024 + 16384 + 512) * 4)   // 71680

__device__ __align__(16) __half g_h[NPROTO * DIM];   // fp16 high split of w
__device__ __align__(16) float  g_wf[NPROTO * DIM];  // exact fp32 w
__device__ float g_bias[NPROTO];
__device__ int   g_maxMw = 0;
__device__ int   g_maxW  = 0;
__device__ int   g_nflag;
__device__ int   g_list[BATCH];

// ---------------- helpers ----------------
__device__ __forceinline__ uint32_t smem_u32(const void* p) {
    uint32_t a;
    asm("{ .reg .u64 t; cvta.to.shared.u64 t, %1; cvt.u32.u64 %0, t; }" : "=r"(a) : "l"(p));
    return a;
}
__device__ __forceinline__ void ldsm4(uint32_t* r, uint32_t a) {
    asm volatile("ldmatrix.sync.aligned.m8n8.x4.shared.b16 {%0,%1,%2,%3}, [%4];"
                 : "=r"(r[0]), "=r"(r[1]), "=r"(r[2]), "=r"(r[3]) : "r"(a));
}
__device__ __forceinline__ void mma16816(float* d, const uint32_t* a, const uint32_t* b) {
    asm volatile(
        "mma.sync.aligned.m16n8k16.row.col.f32.f16.f16.f32 "
        "{%0,%1,%2,%3}, {%4,%5,%6,%7}, {%8,%9}, {%0,%1,%2,%3};"
        : "+f"(d[0]), "+f"(d[1]), "+f"(d[2]), "+f"(d[3])
        : "r"(a[0]), "r"(a[1]), "r"(a[2]), "r"(a[3]), "r"(b[0]), "r"(b[1]));
}
__device__ __forceinline__ void cp_async16(uint32_t dst, const void* src) {
    asm volatile("cp.async.cg.shared.global [%0], [%1], 16;" :: "r"(dst), "l"(src));
}

// ---------------------------------------------------------------------------
// Prep
// ---------------------------------------------------------------------------
__global__ void prep_kernel(const float* __restrict__ protos,
                            const float* __restrict__ relevance) {
    int p = blockIdx.x;
    int d = threadIdx.x;
    if (p == 0 && d == 0) g_nflag = 0;

    float r  = relevance[d];
    float pv = protos[p * DIM + d];
    float w  = r * r * pv;

    __half h  = __float2half_rn(w);
    float  Mw = w - __half2float(h);
    g_h[p * DIM + d]  = h;
    g_wf[p * DIM + d] = w;

    float sb = w * pv, sm = Mw * Mw, sw = w * w;
    __shared__ float r0[4], r1[4], r2[4];
    #pragma unroll
    for (int off = 16; off > 0; off >>= 1) {
        sb += __shfl_down_sync(0xffffffffu, sb, off);
        sm += __shfl_down_sync(0xffffffffu, sm, off);
        sw += __shfl_down_sync(0xffffffffu, sw, off);
    }
    if ((d & 31) == 0) { r0[d >> 5] = sb; r1[d >> 5] = sm; r2[d >> 5] = sw; }
    __syncthreads();
    if (d == 0) {
        g_bias[p] = -0.5f * (r0[0] + r0[1] + r0[2] + r0[3]);
        float nm = sqrtf(r1[0] + r1[1] + r1[2] + r1[3]) * 1.0001f;
        float nw = sqrtf(r2[0] + r2[1] + r2[2] + r2[3]) * 1.0001f;
        atomicMax(&g_maxMw, __float_as_int(nm));
        atomicMax(&g_maxW,  __float_as_int(nw));
    }
}

// ---------------------------------------------------------------------------
// Phase 1: hh-only fp16 GEMM (NCHUNK=64) + tournament top-2 + certification.
// ---------------------------------------------------------------------------
extern __shared__ char smem[];

__global__ void __launch_bounds__(NTHREADS, 2)
grlvq_phase1(const float* __restrict__ x,
             const float* __restrict__ proto_out,
             float* __restrict__ out) {
    const uint32_t sb = smem_u32(smem);
    const int tid  = threadIdx.x;
    const int wid  = tid >> 5;
    const int lane = tid & 31;
    const int row0 = blockIdx.x * MTILE;
    const int wm = (wid & 3) * 32;
    const int wn = (wid >> 2) * 32;

    for (int i = tid; i < NPROTO; i += NTHREADS)
        ((float*)(smem + SM_BIAS))[i] = g_bias[i];

    #define ISSUE_B(c, buf)                                                        \
        do {                                                                       \
            for (int i = tid; i < 1024; i += NTHREADS) {                           \
                int rr = i >> 4, q = i & 15;                                       \
                const void* src = &g_h[(size_t)((c) * NCHUNK + rr) * DIM + q * 8]; \
                uint32_t dst = sb + SM_B + (buf) * BTILE + rr * ASTRIDE + q * 16;  \
                cp_async16(dst, src);                                              \
            }                                                                      \
            asm volatile("cp.async.commit_group;" ::: "memory");                   \
        } while (0)

    ISSUE_B(0, 0);
    ISSUE_B(1, 1);

    // ---- A tile: fp16 high split; row norms for bound ----
    {
        const int r  = tid >> 1;
        const int cb = (tid & 1) * 64;
        const float4* xr = (const float4*)(x + (size_t)(row0 + r) * DIM + cb);
        float sx2 = 0.0f, sm2 = 0.0f;
        #pragma unroll
        for (int g = 0; g < 8; g++) {
            float4 v0 = xr[g * 2], v1 = xr[g * 2 + 1];
            float xv[8] = {v0.x, v0.y, v0.z, v0.w, v1.x, v1.y, v1.z, v1.w};
            uint32_t hh[4];
            #pragma unroll
            for (int q = 0; q < 4; q++) {
                float a0 = xv[2 * q], a1 = xv[2 * q + 1];
                __half h0 = __float2half_rn(a0), h1 = __float2half_rn(a1);
                float m0 = a0 - __half2float(h0), m1 = a1 - __half2float(h1);
                sx2 += a0 * a0 + a1 * a1;
                sm2 += m0 * m0 + m1 * m1;
                hh[q] = ((uint32_t)__half_as_ushort(h1) << 16) | __half_as_ushort(h0);
            }
            uint32_t off = (uint32_t)r * ASTRIDE + (uint32_t)(cb + g * 8) * 2;
            *(uint4*)(smem + SM_A + off) = make_uint4(hh[0], hh[1], hh[2], hh[3]);
        }
        sx2 += __shfl_xor_sync(0xffffffffu, sx2, 1);
        sm2 += __shfl_xor_sync(0xffffffffu, sm2, 1);
        if ((tid & 1) == 0) {
            float maxMw = __int_as_float(g_maxMw);
            float maxW  = __int_as_float(g_maxW);
            ((float*)(smem + SM_NRM))[r] =
                1.0002f * sqrtf(sx2) * maxMw + 1.0002f * sqrtf(sm2) * maxW + 0.01f;
        }
    }

    float v1s[4], v2s[4];
    int   i1s[4];
    #pragma unroll
    for (int i = 0; i < 4; i++) { v1s[i] = -3.4e38f; v2s[i] = -3.4e38f; i1s[i] = 0; }

    const uint32_t a_row = (uint32_t)(wm + (lane & 15));
    const uint32_t a_kh  = (uint32_t)(lane >> 4) * 16;
    const uint32_t b_row = (uint32_t)(wn + ((lane >> 4) & 1) * 8 + (lane & 7));
    const uint32_t b_kh  = (uint32_t)((lane >> 3) & 1) * 16;

    for (int c = 0; c < NCHUNKS; c++) {
        asm volatile("cp.async.wait_group 1;" ::: "memory");
        __syncthreads();
        const uint32_t bbase = sb + SM_B + (c & 1) * BTILE;

        float acc[2][4][4];
        #pragma unroll
        for (int mt = 0; mt < 2; mt++)
            #pragma unroll
            for (int nt = 0; nt < 4; nt++)
                #pragma unroll
                for (int j = 0; j < 4; j++) acc[mt][nt][j] = 0.0f;

        #pragma unroll
        for (int kk = 0; kk < 8; kk++) {
            uint32_t af[2][4], bf[2][4];
            #pragma unroll
            for (int mt = 0; mt < 2; mt++)
                ldsm4(af[mt], sb + SM_A + (a_row + mt * 16) * ASTRIDE + kk * 32 + a_kh);
            #pragma unroll
            for (int np = 0; np < 2; np++)
                ldsm4(bf[np], bbase + (b_row + np * 16) * ASTRIDE + kk * 32 + b_kh);
            #pragma unroll
            for (int mt = 0; mt < 2; mt++)
                #pragma unroll
                for (int nt = 0; nt < 4; nt++)
                    mma16816(acc[mt][nt], af[mt], &bf[nt >> 1][(nt & 1) * 2]);
        }

        // ---- epilogue: hoisted bias + exact 4-value tournament top-2 ----
        const float* bias_s = (const float*)(smem + SM_BIAS);
        const int cbase = c * NCHUNK + wn + (lane & 3) * 2;
        float bb[8];
        #pragma unroll
        for (int g = 0; g < 2; g++) {
            bb[g * 4 + 0] = bias_s[cbase + g * 16 + 0];
            bb[g * 4 + 1] = bias_s[cbase + g * 16 + 1];
            bb[g * 4 + 2] = bias_s[cbase + g * 16 + 8];
            bb[g * 4 + 3] = bias_s[cbase + g * 16 + 9];
        }
        #pragma unroll
        for (int mt = 0; mt < 2; mt++) {
            #pragma unroll
            for (int h = 0; h < 2; h++) {        // rows r, r+8
                const int s = mt * 2 + h;
                #pragma unroll
                for (int g = 0; g < 2; g++) {    // nt pairs (0,1), (2,3)
                    // ascending columns: c0 < c0+1 < c0+8 < c0+9
                    const int c0 = cbase + g * 16;
                    float v0 = acc[mt][2 * g + 0][2 * h + 0] + bb[g * 4 + 0];
                    float v1 = acc[mt][2 * g + 0][2 * h + 1] + bb[g * 4 + 1];
                    float v2 = acc[mt][2 * g + 1][2 * h + 0] + bb[g * 4 + 2];
                    float v3 = acc[mt][2 * g + 1][2 * h + 1] + bb[g * 4 + 3];
                    float a  = fmaxf(v0, v1), b = fminf(v0, v1);
                    float cc = fmaxf(v2, v3), d = fminf(v2, v3);
                    float m1 = fmaxf(a, cc);
                    float m2 = fmaxf(fminf(a, cc), fmaxf(b, d));   // exact 2nd of 4
                    int iab = (v1 > v0) ? c0 + 1 : c0;
                    int icd = (v3 > v2) ? c0 + 9 : c0 + 8;
                    int ig  = (cc > a) ? icd : iab;
                    v2s[s] = fmaxf(fminf(v1s[s], m1), fmaxf(v2s[s], m2));
                    i1s[s] = (m1 > v1s[s]) ? ig : i1s[s];
                    v1s[s] = fmaxf(v1s[s], m1);
                }
            }
        }

        __syncthreads();
        if (c + 2 < NCHUNKS) ISSUE_B(c + 2, c & 1);
    }

    // ---- cross-thread top-2 merge: 8 owners per row ----
    float* rv1 = (float*)(smem + SM_RED);
    int*   ri1 = (int*)(smem + SM_RED + 4096);
    float* rv2 = (float*)(smem + SM_RED + 8192);
    const int slot = ((wid >> 2) << 2) | (lane & 3);
    #pragma unroll
    for (int sl = 0; sl < 4; sl++) {
        int row = wm + (sl >> 1) * 16 + (sl & 1) * 8 + (lane >> 2);
        rv1[row * 8 + slot] = v1s[sl];
        ri1[row * 8 + slot] = i1s[sl];
        rv2[row * 8 + slot] = v2s[sl];
    }
    __syncthreads();

    if (tid < MTILE) {
        float b1 = -3.4e38f, b2 = -3.4e38f;
        int   bi = 0;
        #pragma unroll
        for (int j = 0; j < 8; j++) {
            float v = rv1[tid * 8 + j];
            int  ix = ri1[tid * 8 + j];
            bool g = v > b1;
            b2 = fmaxf(b2, fminf(v, b1));
            b1 = fmaxf(b1, v);
            bi = g ? ix : bi;
        }
        #pragma unroll
        for (int j = 0; j < 8; j++)
            b2 = fmaxf(b2, rv2[tid * 8 + j]);

        float Br = ((const float*)(smem + SM_NRM))[tid];
        bool flag = !(b1 - b2 > 2.0f * Br);

        unsigned m = __ballot_sync(0xffffffffu, flag);
        int cnt = __popc(m);
        if (cnt) {
            int base = 0;
            if (lane == 0) base = atomicAdd(&g_nflag, cnt);
            base = __shfl_sync(0xffffffffu, base, 0);
            if (flag)
                g_list[base + __popc(m & ((1u << lane) - 1u))] = row0 + tid;
        }

        const float4* po = (const float4*)proto_out;
        float4* o = (float4*)(out + (size_t)(row0 + tid) * ODIM);
        o[0] = po[bi * 2];
        o[1] = po[bi * 2 + 1];
    }
}

// ---------------------------------------------------------------------------
// Phase 2: exact fp32 rescore of flagged rows, 8 rows/block, warp-per-row.
// ---------------------------------------------------------------------------
extern __shared__ float s2[];

__global__ void __launch_bounds__(256)
grlvq_phase2(const float* __restrict__ x,
             const float* __restrict__ proto_out,
             float* __restrict__ out) {
    float* sx    = s2;                     // 8 x 128
    float* sw    = s2 + 1024;              // [128 dims][128 protos]
    float* sbias = s2 + 1024 + 16384;      // 512

    const int tid  = threadIdx.x;
    const int wid  = tid >> 5;
    const int lane = tid & 31;
    const int nflag = g_nflag;

    for (int i = tid; i < NPROTO; i += 256) sbias[i] = g_bias[i];

    for (int base = blockIdx.x * P2ROWS; base < nflag; base += P2BLOCKS * P2ROWS) {
        __syncthreads();
        const int nr = min(P2ROWS, nflag - base);

        if (tid < nr * 32) {
            int r = tid >> 5, q = tid & 31;
            int row = g_list[base + r];
            ((float4*)sx)[tid] = ((const float4*)(x + (size_t)row * DIM))[q];
        }

        float bv = -3.4e38f;
        int   bi = 0;

        for (int c = 0; c < 4; c++) {
            __syncthreads();
            {   // transpose-load w chunk: sw[d][p]
                int pr = tid >> 1;
                int d0 = (tid & 1) * 64;
                const float4* wsrc =
                    (const float4*)&g_wf[(size_t)(c * 128 + pr) * DIM + d0];
                #pragma unroll
                for (int q = 0; q < 16; q++) {
                    float4 v = wsrc[q];
                    int d = d0 + q * 4;
                    sw[(d + 0) * 128 + pr] = v.x;
                    sw[(d + 1) * 128 + pr] = v.y;
                    sw[(d + 2) * 128 + pr] = v.z;
                    sw[(d + 3) * 128 + pr] = v.w;
                }
            }
            __syncthreads();

            float a0 = 0.f, a1 = 0.f, a2 = 0.f, a3 = 0.f;
            #pragma unroll 8
            for (int dd = 0; dd < 128; dd++) {
                float xv = sx[wid * 128 + dd];
                float4 w = *(const float4*)&sw[dd * 128 + lane * 4];
                a0 += xv * w.x; a1 += xv * w.y; a2 += xv * w.z; a3 += xv * w.w;
            }
            int p = c * 128 + lane * 4;
            float s0 = a0 + sbias[p];
            float s1 = a1 + sbias[p + 1];
            float s2v = a2 + sbias[p + 2];
            float s3 = a3 + sbias[p + 3];
            if (s0 > bv) { bv = s0; bi = p; }
            if (s1 > bv) { bv = s1; bi = p + 1; }
            if (s2v > bv) { bv = s2v; bi = p + 2; }
            if (s3 > bv) { bv = s3; bi = p + 3; }
        }

        #pragma unroll
        for (int off = 16; off > 0; off >>= 1) {
            float ov = __shfl_down_sync(0xffffffffu, bv, off);
            int   oi = __shfl_down_sync(0xffffffffu, bi, off);
            if (ov > bv || (ov == bv && oi < bi)) { bv = ov; bi = oi; }
        }
        bi = __shfl_sync(0xffffffffu, bi, 0);

        if (wid < nr && lane < 2) {
            int row = g_list[base + wid];
            const float4* po = (const float4*)proto_out;
            ((float4*)(out + (size_t)row * ODIM))[lane] = po[bi * 2 + lane];
        }
    }
}

// ---------------------------------------------------------------------------
extern "C" void kernel_launch(void* const* d_in, const int* in_sizes, int n_in,
                              void* d_out, int out_size) {
    const float* x         = (const float*)d_in[0];
    const float* protos    = (const float*)d_in[1];
    const float* proto_out = (const float*)d_in[2];
    const float* relevance = (const float*)d_in[3];
    float* out = (float*)d_out;

    prep_kernel<<<NPROTO, DIM>>>(protos, relevance);

    cudaFuncSetAttribute(grlvq_phase1,
                         cudaFuncAttributeMaxDynamicSharedMemorySize, SMEM_TOTAL);
    grlvq_phase1<<<BATCH / MTILE, NTHREADS, SMEM_TOTAL>>>(x, proto_out, out);

    cudaFuncSetAttribute(grlvq_phase2,
                         cudaFuncAttributeMaxDynamicSharedMemorySize, P2SMEM);
    grlvq_phase2<<<P2BLOCKS, 256, P2SMEM>>>(x, proto_out, out);
}